// round 8
// baseline (speedup 1.0000x reference)
#include <cuda_runtime.h>
#include <cuda_bf16.h>
#include <cstdint>

#define BATCH 128
#define CH    128
#define NN    170
#define TT    12
#define NP    176          // padded node pitch
#define SCP   172          // score smem pitch (bf16)
#define PN2   14450        // u32 words per batch in g_P (= 170*170/2)

static __device__ __align__(16) float    g_xs[BATCH * CH * NP];        // t-reduced x (f32)
static __device__ __align__(16) unsigned g_EdB[BATCH * NN * (NP/2)];   // E_d^T bf16 pairs
static __device__ __align__(16) unsigned g_P[BATCH * PN2];             // per-batch probs bf16x2

// k_gemm1 smem: es bf16-pairs [128][88 u32] + xs f32 [128][88]
#define SMEM_G1 ((11264 + 11264) * 4)                  // 90,112 B -> 2 CTA/SM
// k_adj smem: ed f32 [170][176] + sc bf16 [170][172]
#define SMEM_A  (NN * NP * 4 + NN * SCP * 2)           // 178,160 B

// ------------------------------------------------------- packed f32x2 helpers
typedef unsigned long long u64t;

__device__ __forceinline__ u64t splat2(float v) {
    u64t d; asm("mov.b64 %0, {%1, %1};" : "=l"(d) : "f"(v)); return d;
}
__device__ __forceinline__ u64t splat2u(unsigned v) {     // f32 bits in u32
    u64t d; asm("mov.b64 %0, {%1, %1};" : "=l"(d) : "r"(v)); return d;
}
__device__ __forceinline__ void ffma2(u64t& c, u64t a, u64t b) {
    asm("fma.rn.f32x2 %0, %1, %2, %3;" : "=l"(c) : "l"(a), "l"(b), "l"(c));
}
__device__ __forceinline__ void unpack2(float& lo, float& hi, u64t v) {
    asm("mov.b64 {%0, %1}, %2;" : "=f"(lo), "=f"(hi) : "l"(v));
}
__device__ __forceinline__ float tanh_ap(float x) {
    float r; asm("tanh.approx.f32 %0, %1;" : "=f"(r) : "f"(x)); return r;
}
__device__ __forceinline__ float bf_lo(unsigned w) { return __uint_as_float(w << 16); }
__device__ __forceinline__ float bf_hi(unsigned w) { return __uint_as_float(w & 0xFFFF0000u); }
__device__ __forceinline__ unsigned bf_pack(float a, float b) {
    __nv_bfloat162 h = __floats2bfloat162_rn(a, b);
    return *reinterpret_cast<unsigned*>(&h);
}

// ------------------------------------ K_load: streaming t-reduction x -> g_xs
__global__ void k_load(const float* __restrict__ x) {
    const int total = BATCH * CH * NP;
    for (int i = blockIdx.x * blockDim.x + threadIdx.x; i < total;
         i += gridDim.x * blockDim.x) {
        int np = i % NP;
        int bc = i / NP;
        float s = 0.0f;
        if (np < NN) {
            const float4* p = reinterpret_cast<const float4*>(
                x + ((size_t)bc * NN + np) * TT);
            float4 v0 = __ldcs(p), v1 = __ldcs(p + 1), v2 = __ldcs(p + 2);
            s = ((v0.x + v0.y) + (v0.z + v0.w))
              + ((v1.x + v1.y) + (v1.z + v1.w))
              + ((v2.x + v2.y) + (v2.z + v2.w));
        }
        g_xs[i] = s;
    }
}

// --------------- K_gemm1: ed[m][n] = tanh(sum_c Es[c][m] * xs[c][n])  (8x8)
// grid (128 batches, 2 n-halves), 256 threads, 242 cells of 8m x 8n each.
__global__ void __launch_bounds__(256, 2) k_gemm1(const float* __restrict__ Es) {
    extern __shared__ float smf[];
    unsigned* es = reinterpret_cast<unsigned*>(smf);   // bf16x2 [128][88]
    float* xs = smf + CH * 88;                         // f32 [128][88]
    const int tid = threadIdx.x;
    const int b = blockIdx.x, h = blockIdx.y;

    // stage Es as packed bf16 pairs: es[c][mp] = {Es[c][2mp], Es[c][2mp+1]}
    for (int i = tid; i < CH * 88; i += 256) {
        int c = i / 88, mp = i - c * 88;
        int m0 = mp * 2;
        float f0 = 0.f, f1 = 0.f;
        if (m0 < NN) {
            float2 e = *reinterpret_cast<const float2*>(Es + c * NN + m0);
            f0 = e.x; f1 = e.y;
        }
        es[i] = bf_pack(f0, f1);
    }
    // stage xs half (f32, from L2-resident g_xs), vectorized
    {
        const float* src = g_xs + (size_t)b * CH * NP + 88 * h;
        for (int i = tid; i < CH * 22; i += 256) {
            int c = i / 22, q = i - c * 22;
            reinterpret_cast<float4*>(xs)[c * 22 + q] =
                *reinterpret_cast<const float4*>(src + (size_t)c * NP + q * 4);
        }
    }
    __syncthreads();

    // 22 m-strips(8) x 11 n-strips(8) = 242 cells; 1 per thread
    const int cell = tid;
    if (cell < 242) {
        const int smi = cell / 11, snj = cell - smi * 11;
        const int am = smi * 8, bn = snj * 8;
        u64t acc[8][4];
        #pragma unroll
        for (int i = 0; i < 8; i++)
            #pragma unroll
            for (int j = 0; j < 4; j++) acc[i][j] = 0ull;

        const unsigned* ep = es + (am >> 1);
        const float* bp = xs + bn;
        #pragma unroll 2
        for (int c = 0; c < CH; c++) {
            uint4 ev = *reinterpret_cast<const uint4*>(ep + c * 88);
            ulonglong2 b01 = *reinterpret_cast<const ulonglong2*>(bp + c * 88);
            ulonglong2 b23 = *reinterpret_cast<const ulonglong2*>(bp + c * 88 + 4);
            unsigned ew[4] = {ev.x, ev.y, ev.z, ev.w};
            #pragma unroll
            for (int q = 0; q < 4; q++) {
                u64t s0 = splat2u(ew[q] << 16);
                u64t s1 = splat2u(ew[q] & 0xFFFF0000u);
                ffma2(acc[2*q][0], s0, b01.x);  ffma2(acc[2*q][1], s0, b01.y);
                ffma2(acc[2*q][2], s0, b23.x);  ffma2(acc[2*q][3], s0, b23.y);
                ffma2(acc[2*q+1][0], s1, b01.x); ffma2(acc[2*q+1][1], s1, b01.y);
                ffma2(acc[2*q+1][2], s1, b23.x); ffma2(acc[2*q+1][3], s1, b23.y);
            }
        }

        // epilogue: tanh -> bf16 pairs -> g_EdB[b][m][(88h+bn)/2 ..]
        #pragma unroll
        for (int mi = 0; mi < 8; mi++) {
            int m = am + mi;
            if (m < NN) {
                float f[8];
                #pragma unroll
                for (int j = 0; j < 4; j++) unpack2(f[2*j], f[2*j+1], acc[mi][j]);
                uint4 o;
                o.x = bf_pack(tanh_ap(f[0]), tanh_ap(f[1]));
                o.y = bf_pack(tanh_ap(f[2]), tanh_ap(f[3]));
                o.z = bf_pack(tanh_ap(f[4]), tanh_ap(f[5]));
                o.w = bf_pack(tanh_ap(f[6]), tanh_ap(f[7]));
                unsigned* dst = g_EdB + ((size_t)b * NN + m) * (NP/2) + ((88*h + bn) >> 1);
                *reinterpret_cast<uint4*>(dst) = o;
            }
        }
    }
}

// -------- K_adj: symmetric GEMM2 (8x8 triangle) + softmax -> g_P (no atomics)
__global__ void __launch_bounds__(512, 1) k_adj() {
    extern __shared__ float sm[];
    float* ed = sm;                                          // [170][176] f32
    __nv_bfloat16* sc = reinterpret_cast<__nv_bfloat16*>(sm + NN * NP);
    const int tid = threadIdx.x;
    const int b = blockIdx.x;

    // copy-in: bf16 -> f32 expansion (170*176 bf16 = 3740 uint4)
    {
        const uint4* src = reinterpret_cast<const uint4*>(g_EdB + (size_t)b * NN * (NP/2));
        for (int i = tid; i < (NN * NP) / 8; i += 512) {
            uint4 v = src[i];
            float4 f0, f1;
            f0.x = bf_lo(v.x); f0.y = bf_hi(v.x); f0.z = bf_lo(v.y); f0.w = bf_hi(v.y);
            f1.x = bf_lo(v.z); f1.y = bf_hi(v.z); f1.z = bf_lo(v.w); f1.w = bf_hi(v.w);
            reinterpret_cast<float4*>(ed)[2*i]   = f0;
            reinterpret_cast<float4*>(ed)[2*i+1] = f1;
        }
    }
    __syncthreads();

    // 22 strips of 8: triangle pairs (si >= sj) -> 253 blocks, 1 per thread
    const float scale = 0.08838834764831843f;                // 1/sqrt(128)
    const int cell = tid;
    if (cell < 253) {
        int si = (int)((sqrtf(8.0f * (float)cell + 1.0f) - 1.0f) * 0.5f);
        while ((si + 1) * (si + 2) / 2 <= cell) si++;
        while (si * (si + 1) / 2 > cell) si--;
        const int sj = cell - si * (si + 1) / 2;
        const int n = si * 8, k = sj * 8;

        u64t acc[8][4];                                      // [ki][n-pair]
        #pragma unroll
        for (int i = 0; i < 8; i++)
            #pragma unroll
            for (int j = 0; j < 4; j++) acc[i][j] = 0ull;

        #pragma unroll 2
        for (int m = 0; m < NN; m++) {
            const float* row = ed + m * NP;
            ulonglong2 a01 = *reinterpret_cast<const ulonglong2*>(row + n);
            ulonglong2 a23 = *reinterpret_cast<const ulonglong2*>(row + n + 4);
            float4 k0 = *reinterpret_cast<const float4*>(row + k);
            float4 k1 = *reinterpret_cast<const float4*>(row + k + 4);
            float kv[8] = {k0.x, k0.y, k0.z, k0.w, k1.x, k1.y, k1.z, k1.w};
            #pragma unroll
            for (int ki = 0; ki < 8; ki++) {
                u64t s = splat2(kv[ki]);
                ffma2(acc[ki][0], s, a01.x); ffma2(acc[ki][1], s, a01.y);
                ffma2(acc[ki][2], s, a23.x); ffma2(acc[ki][3], s, a23.y);
            }
        }

        #pragma unroll
        for (int ki = 0; ki < 8; ki++) {
            int kk = k + ki;
            if (kk >= NN) continue;
            #pragma unroll
            for (int j = 0; j < 4; j++) {
                float v0, v1;
                unpack2(v0, v1, acc[ki][j]);
                int n0 = n + 2 * j, n1 = n0 + 1;
                __nv_bfloat16 h0 = __float2bfloat16(fmaxf(0.0f, v0 * scale));
                __nv_bfloat16 h1 = __float2bfloat16(fmaxf(0.0f, v1 * scale));
                if (n0 < NN) { sc[n0 * SCP + kk] = h0; sc[kk * SCP + n0] = h0; }
                if (n1 < NN) { sc[n1 * SCP + kk] = h1; sc[kk * SCP + n1] = h1; }
            }
        }
    }
    __syncthreads();

    // row softmax (scores in [0,~15.1] -> no max pass); write bf16x2 to g_P
    const int wid = tid >> 5, lane = tid & 31;
    for (int n = wid; n < NN; n += 16) {
        const unsigned* row32 = reinterpret_cast<const unsigned*>(sc + n * SCP);
        float ssum = 0.0f;
        for (int kq = lane; kq < 85; kq += 32) {
            unsigned w = row32[kq];
            ssum += __expf(bf_lo(w)) + __expf(bf_hi(w));
        }
        #pragma unroll
        for (int o = 16; o; o >>= 1)
            ssum += __shfl_xor_sync(0xffffffffu, ssum, o);
        float inv = 1.0f / ssum;
        unsigned* dst = g_P + (size_t)b * PN2 + n * 85;
        for (int kq = lane; kq < 85; kq += 32) {
            unsigned w = row32[kq];
            dst[kq] = bf_pack(__expf(bf_lo(w)) * inv, __expf(bf_hi(w)) * inv);
        }
    }
}

// ----------------- K_thresh: batch-sum of g_P + threshold (2 outputs/thread)
__global__ void k_thresh(float* __restrict__ out) {
    int i = blockIdx.x * blockDim.x + threadIdx.x;
    if (i < PN2) {
        float s0 = 0.0f, s1 = 0.0f;
        const unsigned* p = g_P + i;
        #pragma unroll 8
        for (int b = 0; b < BATCH; b++) {
            unsigned w = p[(size_t)b * PN2];
            s0 += bf_lo(w); s1 += bf_hi(w);
        }
        float2 o;
        o.x = (s0 > 64.0f) ? 1.0f : 0.0f;    // mean > 0.5
        o.y = (s1 > 64.0f) ? 1.0f : 0.0f;
        reinterpret_cast<float2*>(out)[i] = o;
    }
}

// ------------------------------------------------------------------- launcher
extern "C" void kernel_launch(void* const* d_in, const int* in_sizes, int n_in,
                              void* d_out, int out_size) {
    const float* x  = (const float*)d_in[0];   // [128,128,170,12] f32
    const float* Es = (const float*)d_in[1];   // [128,170] f32
    float* out = (float*)d_out;                // [170,170] f32

    cudaFuncSetAttribute(k_gemm1, cudaFuncAttributeMaxDynamicSharedMemorySize, SMEM_G1);
    cudaFuncSetAttribute(k_adj,   cudaFuncAttributeMaxDynamicSharedMemorySize, SMEM_A);

    k_load<<<592, 256>>>(x);
    dim3 g1(BATCH, 2);
    k_gemm1<<<g1, 256, SMEM_G1>>>(Es);
    k_adj<<<BATCH, 512, SMEM_A>>>();
    k_thresh<<<(PN2 + 255) / 256, 256>>>(out);
}

// round 9
// speedup vs baseline: 1.0513x; 1.0513x over previous
#include <cuda_runtime.h>
#include <cuda_bf16.h>
#include <cstdint>

#define BATCH 128
#define CH    128
#define NN    170
#define TT    12
#define NP    176          // padded node pitch
#define SCP   172          // score smem pitch (bf16)

static __device__ __align__(16) float    g_xs[BATCH * CH * NP];        // t-reduced x
static __device__ __align__(16) unsigned g_EdB[BATCH * NN * (NP/2)];   // E_d^T bf16 pairs
static __device__ float g_Asum[NN * NN];

// k_gemm1 smem: es bf16-pairs [128][88 u32] + xs f32 [128][88]
#define SMEM_G1 ((11264 + 11264) * 4)                  // 90,112 B -> 2 CTA/SM
// k_adj smem: ed f32 [170][176] + sc bf16 [170][172]
#define SMEM_A  (NN * NP * 4 + NN * SCP * 2)           // 178,160 B

// ------------------------------------------------------- packed f32x2 helpers
typedef unsigned long long u64t;

__device__ __forceinline__ u64t splat2(float v) {
    u64t d; asm("mov.b64 %0, {%1, %1};" : "=l"(d) : "f"(v)); return d;
}
__device__ __forceinline__ u64t splat2u(unsigned v) {     // f32 bits in u32
    u64t d; asm("mov.b64 %0, {%1, %1};" : "=l"(d) : "r"(v)); return d;
}
__device__ __forceinline__ void ffma2(u64t& c, u64t a, u64t b) {
    asm("fma.rn.f32x2 %0, %1, %2, %3;" : "=l"(c) : "l"(a), "l"(b), "l"(c));
}
__device__ __forceinline__ void unpack2(float& lo, float& hi, u64t v) {
    asm("mov.b64 {%0, %1}, %2;" : "=f"(lo), "=f"(hi) : "l"(v));
}
__device__ __forceinline__ float tanh_ap(float x) {
    float r; asm("tanh.approx.f32 %0, %1;" : "=f"(r) : "f"(x)); return r;
}
__device__ __forceinline__ float bf_lo(unsigned w) { return __uint_as_float(w << 16); }
__device__ __forceinline__ float bf_hi(unsigned w) { return __uint_as_float(w & 0xFFFF0000u); }
__device__ __forceinline__ unsigned bf_pack(float a, float b) {
    __nv_bfloat162 h = __floats2bfloat162_rn(a, b);
    return *reinterpret_cast<unsigned*>(&h);
}

// ---------------- K_load: coalesced smem-staged t-reduction x -> g_xs
// chunk = 256 elements = 3072 floats = 768 float4, loaded fully coalesced.
__global__ void __launch_bounds__(256) k_load(const float* __restrict__ x) {
    __shared__ float4 st[768];
    const int tid = threadIdx.x;

    // zero the pad columns of g_xs (np in [170,176))
    for (int i = blockIdx.x * 256 + tid; i < BATCH * CH * 6; i += gridDim.x * 256) {
        int bc = i / 6, j = i - bc * 6;
        g_xs[(size_t)bc * NP + NN + j] = 0.0f;
    }

    const int nchunks = (BATCH * CH * NN) / 256;       // 10880 exactly
    const float4* xf4 = reinterpret_cast<const float4*>(x);
    for (int ch = blockIdx.x; ch < nchunks; ch += gridDim.x) {
        size_t base = (size_t)ch * 768;
        st[tid]       = __ldcs(xf4 + base + tid);
        st[tid + 256] = __ldcs(xf4 + base + tid + 256);
        st[tid + 512] = __ldcs(xf4 + base + tid + 512);
        __syncthreads();
        const float4* p = reinterpret_cast<const float4*>(
            reinterpret_cast<const float*>(st) + tid * TT);
        float4 v0 = p[0], v1 = p[1], v2 = p[2];
        float s = ((v0.x + v0.y) + (v0.z + v0.w))
                + ((v1.x + v1.y) + (v1.z + v1.w))
                + ((v2.x + v2.y) + (v2.z + v2.w));
        int e = ch * 256 + tid;
        int bc = e / NN, n = e - bc * NN;
        g_xs[(size_t)bc * NP + n] = s;
        __syncthreads();
    }
}

// --------------- K_gemm1: ed[m][n] = tanh(sum_c Es[c][m] * xs[c][n])  (8x8)
__global__ void __launch_bounds__(256, 2) k_gemm1(const float* __restrict__ Es) {
    extern __shared__ float smf[];
    unsigned* es = reinterpret_cast<unsigned*>(smf);   // bf16x2 [128][88]
    float* xs = smf + CH * 88;                         // f32 [128][88]
    const int tid = threadIdx.x;
    const int b = blockIdx.x, h = blockIdx.y;

    for (int i = tid; i < CH * 88; i += 256) {
        int c = i / 88, mp = i - c * 88;
        int m0 = mp * 2;
        float f0 = 0.f, f1 = 0.f;
        if (m0 < NN) {
            float2 e = *reinterpret_cast<const float2*>(Es + c * NN + m0);
            f0 = e.x; f1 = e.y;
        }
        es[i] = bf_pack(f0, f1);
    }
    {
        const float* src = g_xs + (size_t)b * CH * NP + 88 * h;
        for (int i = tid; i < CH * 22; i += 256) {
            int c = i / 22, q = i - c * 22;
            reinterpret_cast<float4*>(xs)[c * 22 + q] =
                *reinterpret_cast<const float4*>(src + (size_t)c * NP + q * 4);
        }
    }
    __syncthreads();

    const int cell = tid;
    if (cell < 242) {
        const int smi = cell / 11, snj = cell - smi * 11;
        const int am = smi * 8, bn = snj * 8;
        u64t acc[8][4];
        #pragma unroll
        for (int i = 0; i < 8; i++)
            #pragma unroll
            for (int j = 0; j < 4; j++) acc[i][j] = 0ull;

        const unsigned* ep = es + (am >> 1);
        const float* bp = xs + bn;
        #pragma unroll 2
        for (int c = 0; c < CH; c++) {
            uint4 ev = *reinterpret_cast<const uint4*>(ep + c * 88);
            ulonglong2 b01 = *reinterpret_cast<const ulonglong2*>(bp + c * 88);
            ulonglong2 b23 = *reinterpret_cast<const ulonglong2*>(bp + c * 88 + 4);
            unsigned ew[4] = {ev.x, ev.y, ev.z, ev.w};
            #pragma unroll
            for (int q = 0; q < 4; q++) {
                u64t s0 = splat2u(ew[q] << 16);
                u64t s1 = splat2u(ew[q] & 0xFFFF0000u);
                ffma2(acc[2*q][0], s0, b01.x);  ffma2(acc[2*q][1], s0, b01.y);
                ffma2(acc[2*q][2], s0, b23.x);  ffma2(acc[2*q][3], s0, b23.y);
                ffma2(acc[2*q+1][0], s1, b01.x); ffma2(acc[2*q+1][1], s1, b01.y);
                ffma2(acc[2*q+1][2], s1, b23.x); ffma2(acc[2*q+1][3], s1, b23.y);
            }
        }

        #pragma unroll
        for (int mi = 0; mi < 8; mi++) {
            int m = am + mi;
            if (m < NN) {
                float f[8];
                #pragma unroll
                for (int j = 0; j < 4; j++) unpack2(f[2*j], f[2*j+1], acc[mi][j]);
                uint4 o;
                o.x = bf_pack(tanh_ap(f[0]), tanh_ap(f[1]));
                o.y = bf_pack(tanh_ap(f[2]), tanh_ap(f[3]));
                o.z = bf_pack(tanh_ap(f[4]), tanh_ap(f[5]));
                o.w = bf_pack(tanh_ap(f[6]), tanh_ap(f[7]));
                unsigned* dst = g_EdB + ((size_t)b * NN + m) * (NP/2) + ((88*h + bn) >> 1);
                *reinterpret_cast<uint4*>(dst) = o;
            }
        }
    }
}

// -------- K_adj: symmetric GEMM2 (8x8 triangle) + softmax + atomic accumulate
__global__ void __launch_bounds__(512, 1) k_adj() {
    extern __shared__ float sm[];
    float* ed = sm;                                          // [170][176] f32
    __nv_bfloat16* sc = reinterpret_cast<__nv_bfloat16*>(sm + NN * NP);
    const int tid = threadIdx.x;
    const int b = blockIdx.x;

    // copy-in: bf16 -> f32 expansion
    {
        const uint4* src = reinterpret_cast<const uint4*>(g_EdB + (size_t)b * NN * (NP/2));
        for (int i = tid; i < (NN * NP) / 8; i += 512) {
            uint4 v = src[i];
            float4 f0, f1;
            f0.x = bf_lo(v.x); f0.y = bf_hi(v.x); f0.z = bf_lo(v.y); f0.w = bf_hi(v.y);
            f1.x = bf_lo(v.z); f1.y = bf_hi(v.z); f1.z = bf_lo(v.w); f1.w = bf_hi(v.w);
            reinterpret_cast<float4*>(ed)[2*i]   = f0;
            reinterpret_cast<float4*>(ed)[2*i+1] = f1;
        }
    }
    __syncthreads();

    const float scale = 0.08838834764831843f;                // 1/sqrt(128)
    const int cell = tid;
    if (cell < 253) {
        int si = (int)((sqrtf(8.0f * (float)cell + 1.0f) - 1.0f) * 0.5f);
        while ((si + 1) * (si + 2) / 2 <= cell) si++;
        while (si * (si + 1) / 2 > cell) si--;
        const int sj = cell - si * (si + 1) / 2;
        const int n = si * 8, k = sj * 8;

        u64t acc[8][4];
        #pragma unroll
        for (int i = 0; i < 8; i++)
            #pragma unroll
            for (int j = 0; j < 4; j++) acc[i][j] = 0ull;

        #pragma unroll 2
        for (int m = 0; m < NN; m++) {
            const float* row = ed + m * NP;
            ulonglong2 a01 = *reinterpret_cast<const ulonglong2*>(row + n);
            ulonglong2 a23 = *reinterpret_cast<const ulonglong2*>(row + n + 4);
            float4 k0 = *reinterpret_cast<const float4*>(row + k);
            float4 k1 = *reinterpret_cast<const float4*>(row + k + 4);
            float kv[8] = {k0.x, k0.y, k0.z, k0.w, k1.x, k1.y, k1.z, k1.w};
            #pragma unroll
            for (int ki = 0; ki < 8; ki++) {
                u64t s = splat2(kv[ki]);
                ffma2(acc[ki][0], s, a01.x); ffma2(acc[ki][1], s, a01.y);
                ffma2(acc[ki][2], s, a23.x); ffma2(acc[ki][3], s, a23.y);
            }
        }

        #pragma unroll
        for (int ki = 0; ki < 8; ki++) {
            int kk = k + ki;
            if (kk >= NN) continue;
            #pragma unroll
            for (int j = 0; j < 4; j++) {
                float v0, v1;
                unpack2(v0, v1, acc[ki][j]);
                int n0 = n + 2 * j, n1 = n0 + 1;
                __nv_bfloat16 h0 = __float2bfloat16(fmaxf(0.0f, v0 * scale));
                __nv_bfloat16 h1 = __float2bfloat16(fmaxf(0.0f, v1 * scale));
                if (n0 < NN) { sc[n0 * SCP + kk] = h0; sc[kk * SCP + n0] = h0; }
                if (n1 < NN) { sc[n1 * SCP + kk] = h1; sc[kk * SCP + n1] = h1; }
            }
        }
    }
    __syncthreads();

    // row softmax (scores in [0,~15.1] -> no max pass) + atomic accumulate
    const int wid = tid >> 5, lane = tid & 31;
    for (int n = wid; n < NN; n += 16) {
        const __nv_bfloat16* row = sc + n * SCP;
        float ssum = 0.0f;
        for (int kq = lane; kq < NN; kq += 32)
            ssum += __expf(__bfloat162float(row[kq]));
        #pragma unroll
        for (int o = 16; o; o >>= 1)
            ssum += __shfl_xor_sync(0xffffffffu, ssum, o);
        float inv = 1.0f / ssum;
        for (int kq = lane; kq < NN; kq += 32)
            atomicAdd(&g_Asum[n * NN + kq],
                      __expf(__bfloat162float(row[kq])) * inv);
    }
}

// --------------------------------- K_thresh: threshold + self-restore g_Asum
__global__ void k_thresh(float* __restrict__ out) {
    int i = blockIdx.x * blockDim.x + threadIdx.x;
    if (i < NN * NN) {
        out[i] = (g_Asum[i] > 64.0f) ? 1.0f : 0.0f;          // mean > 0.5
        g_Asum[i] = 0.0f;                                    // restore for replay
    }
}

// ------------------------------------------------------------------- launcher
extern "C" void kernel_launch(void* const* d_in, const int* in_sizes, int n_in,
                              void* d_out, int out_size) {
    const float* x  = (const float*)d_in[0];   // [128,128,170,12] f32
    const float* Es = (const float*)d_in[1];   // [128,170] f32
    float* out = (float*)d_out;                // [170,170] f32

    cudaFuncSetAttribute(k_gemm1, cudaFuncAttributeMaxDynamicSharedMemorySize, SMEM_G1);
    cudaFuncSetAttribute(k_adj,   cudaFuncAttributeMaxDynamicSharedMemorySize, SMEM_A);

    k_load<<<1184, 256>>>(x);
    dim3 g1(BATCH, 2);
    k_gemm1<<<g1, 256, SMEM_G1>>>(Es);
    k_adj<<<BATCH, 512, SMEM_A>>>();
    k_thresh<<<(NN * NN + 255) / 256, 256>>>(out);
}